// round 4
// baseline (speedup 1.0000x reference)
#include <cuda_runtime.h>

// Problem constants
#define NN 50000
#define NE 600000

// Float scratch (no zeroing needed: every buffer fully overwritten each replay)
#define OFF_RS_OUT 0
#define OFF_RS_IN  50000
#define OFF_T1     100000            // 50000*64
#define OFF_AGG1   3300000           // 50000*64
#define OFF_T2     6500000           // 50000*32
#define OFF_AGG2   8100000           // 50000*32
#define OFF_T3     9700000           // 50000*32
#define OFF_AGG3   11300000          // 50000*32
#define SCRATCH_TOTAL 12900000       // 51.6 MB

// Int scratch for CSR
#define ICNT_SRC 0                   // 50000 (out-degree counts)
#define ICNT_DST 50000               // 50000 (in-degree counts; consumed by fill)
#define IOFFS    100000              // 50001 (exclusive scan of in-degrees)
#define ICSR     150004              // 600000 (src ids grouped by dst)
#define INT_TOTAL 750004
#define IZERO    100000              // zero [0, IZERO) ints each replay

__device__ __align__(16) float g_scratch[SCRATCH_TOTAL];
__device__ __align__(16) int   g_int[INT_TOTAL];

// ---------------------------------------------------------------------------
// Zero the two count arrays (400 KB)
// ---------------------------------------------------------------------------
__global__ void zero_kernel() {
    int i = blockIdx.x * blockDim.x + threadIdx.x;
    if (i < IZERO / 4) ((int4*)g_int)[i] = make_int4(0, 0, 0, 0);
}

// ---------------------------------------------------------------------------
// Degree / CSR counts
// ---------------------------------------------------------------------------
__global__ void count_kernel(const int* __restrict__ src, const int* __restrict__ dst) {
    int i = blockIdx.x * blockDim.x + threadIdx.x;
    if (i >= NE) return;
    atomicAdd(&g_int[ICNT_SRC + __ldg(&src[i])], 1);
    atomicAdd(&g_int[ICNT_DST + __ldg(&dst[i])], 1);
}

__global__ void rsqrt_kernel() {
    int i = blockIdx.x * blockDim.x + threadIdx.x;
    if (i >= NN) return;
    g_scratch[OFF_RS_OUT + i] = rsqrtf(fmaxf((float)g_int[ICNT_SRC + i], 1.0f));
    g_scratch[OFF_RS_IN  + i] = rsqrtf(fmaxf((float)g_int[ICNT_DST + i], 1.0f));
}

// ---------------------------------------------------------------------------
// Single-block exclusive scan of in-degree counts -> offsets
// ---------------------------------------------------------------------------
#define SCAN_T 1024
#define SCAN_CH ((NN + SCAN_T - 1) / SCAN_T)   // 49
__global__ void __launch_bounds__(SCAN_T) scan_kernel() {
    const int* cnt = g_int + ICNT_DST;
    int* offs = g_int + IOFFS;
    int t = threadIdx.x;
    int lo = t * SCAN_CH;
    int hi = min(lo + SCAN_CH, NN);
    int s = 0;
    for (int i = lo; i < hi; i++) s += cnt[i];

    __shared__ int buf[2][SCAN_T];
    buf[0][t] = s;
    __syncthreads();
    int pi = 0;
    for (int d = 1; d < SCAN_T; d <<= 1) {
        int v = buf[pi][t];
        if (t >= d) v += buf[pi][t - d];
        buf[1 - pi][t] = v;
        pi ^= 1;
        __syncthreads();
    }
    int run = buf[pi][t] - s;   // exclusive base for this thread's chunk
    for (int i = lo; i < hi; i++) { offs[i] = run; run += cnt[i]; }
    if (t == 0) offs[NN] = NE;
}

// ---------------------------------------------------------------------------
// CSR fill: consumes count_dst via atomicSub (rsqrt_kernel must run first)
// ---------------------------------------------------------------------------
__global__ void fill_kernel(const int* __restrict__ src, const int* __restrict__ dst) {
    int i = blockIdx.x * blockDim.x + threadIdx.x;
    if (i >= NE) return;
    int s = __ldg(&src[i]);
    int d = __ldg(&dst[i]);
    int c = atomicSub(&g_int[ICNT_DST + d], 1);
    g_int[ICSR + g_int[IOFFS + d] + c - 1] = s;
}

// ---------------------------------------------------------------------------
// Pull-mode SpMM: agg[n, :] = sum over in-edges of tin[src, :]
// One group of G = F/4 threads per dst node; register accumulate, one store.
// ---------------------------------------------------------------------------
template<int F>
__global__ void __launch_bounds__(256) pull_spmm(const float* __restrict__ tin,
                                                 float* __restrict__ agg)
{
    constexpr int G = F / 4;
    int gid = (blockIdx.x * 256 + threadIdx.x) / G;
    int lane = threadIdx.x % G;
    if (gid >= NN) return;
    int s0 = g_int[IOFFS + gid];
    int s1 = g_int[IOFFS + gid + 1];
    const int* csr = g_int + ICSR;
    float4 acc = make_float4(0.f, 0.f, 0.f, 0.f);
    int j = s0;
    for (; j + 2 <= s1; j += 2) {
        int sa = __ldg(&csr[j]);
        int sb = __ldg(&csr[j + 1]);
        float4 va = __ldg((const float4*)(tin + (size_t)sa * F + 4 * lane));
        float4 vb = __ldg((const float4*)(tin + (size_t)sb * F + 4 * lane));
        acc.x += va.x; acc.y += va.y; acc.z += va.z; acc.w += va.w;
        acc.x += vb.x; acc.y += vb.y; acc.z += vb.z; acc.w += vb.w;
    }
    if (j < s1) {
        int sa = __ldg(&csr[j]);
        float4 va = __ldg((const float4*)(tin + (size_t)sa * F + 4 * lane));
        acc.x += va.x; acc.y += va.y; acc.z += va.z; acc.w += va.w;
    }
    *(float4*)(agg + (size_t)gid * F + 4 * lane) = acc;
}

// ---------------------------------------------------------------------------
// Register-tiled GEMM, transposed X tile (conflict-free LDS.128 everywhere):
//   out[n, :J] = f_out( f_in(X[n, :K]) @ W )
//   Thread tile: TN nodes x 8 columns. sX stored as [k][node], stride NB.
//   MODE_IN : 0 raw, 1 relu(v*rs_in[n] + bin[k]), 2 v*rs_in[n]
//   MODE_OUT: 0 raw, 1 *rs_out[n],               2 +bout[j]
// ---------------------------------------------------------------------------
template<int K, int J, int KC, int TN, int MODE_IN, int MODE_OUT>
__global__ void __launch_bounds__(256) gemm_kernel(
    const float* __restrict__ X, const float* __restrict__ W,
    const float* __restrict__ rs_in, const float* __restrict__ bin,
    const float* __restrict__ rs_out, const float* __restrict__ bout,
    float* __restrict__ out)
{
    constexpr int JV = J / 8;            // column lanes (8 cols each)
    constexpr int NT = 256 / JV;         // thread rows
    constexpr int NB = NT * TN;          // nodes per block
    constexpr int XST = NB;              // transposed row stride

    __shared__ float sW[KC * J];
    __shared__ float sX[KC * XST];       // [k][node]
    __shared__ float sRS[NB];

    const int nrow = threadIdx.x / JV;
    const int jv   = threadIdx.x % JV;
    const int base = blockIdx.x * NB;

    if (MODE_OUT == 1 && threadIdx.x < NB) {
        int n = base + threadIdx.x;
        sRS[threadIdx.x] = (n < NN) ? __ldg(&rs_out[n]) : 0.f;
    }

    float4 acc[TN][2];
    #pragma unroll
    for (int t = 0; t < TN; t++)
        #pragma unroll
        for (int c = 0; c < 2; c++) {
            if (MODE_OUT == 2) acc[t][c] = __ldg((const float4*)&bout[8 * jv + 4 * c]);
            else               acc[t][c] = make_float4(0.f, 0.f, 0.f, 0.f);
        }

    #pragma unroll 1
    for (int k0 = 0; k0 < K; k0 += KC) {
        __syncthreads();
        // Stage W chunk
        for (int i = threadIdx.x; i < KC * J / 4; i += 256)
            ((float4*)sW)[i] = __ldg(&((const float4*)(W + (size_t)k0 * J))[i]);
        // Stage X chunk TRANSPOSED: sX[k][node]
        for (int i = threadIdx.x; i < NB * (KC / 4); i += 256) {
            int nl = i % NB;             // consecutive threads -> consecutive nodes
            int kc = i / NB;
            int n = base + nl;
            float4 v = make_float4(0.f, 0.f, 0.f, 0.f);
            if (n < NN) {
                v = __ldg((const float4*)&X[(size_t)n * K + k0 + 4 * kc]);
                if (MODE_IN == 1) {
                    float r = __ldg(&rs_in[n]);
                    float4 b = __ldg((const float4*)&bin[k0 + 4 * kc]);
                    v.x = fmaxf(fmaf(v.x, r, b.x), 0.f);
                    v.y = fmaxf(fmaf(v.y, r, b.y), 0.f);
                    v.z = fmaxf(fmaf(v.z, r, b.z), 0.f);
                    v.w = fmaxf(fmaf(v.w, r, b.w), 0.f);
                } else if (MODE_IN == 2) {
                    float r = __ldg(&rs_in[n]);
                    v.x *= r; v.y *= r; v.z *= r; v.w *= r;
                }
            }
            sX[(4 * kc + 0) * XST + nl] = v.x;
            sX[(4 * kc + 1) * XST + nl] = v.y;
            sX[(4 * kc + 2) * XST + nl] = v.z;
            sX[(4 * kc + 3) * XST + nl] = v.w;
        }
        __syncthreads();

        #pragma unroll 4
        for (int k = 0; k < KC; k++) {
            float4 w0 = *(const float4*)&sW[k * J + 8 * jv];
            float4 w1 = *(const float4*)&sW[k * J + 8 * jv + 4];
            #pragma unroll
            for (int tt = 0; tt < TN / 4; tt++) {
                float4 xa = *(const float4*)&sX[k * XST + nrow * TN + 4 * tt];
                float xk4[4] = {xa.x, xa.y, xa.z, xa.w};
                #pragma unroll
                for (int q = 0; q < 4; q++) {
                    int t = 4 * tt + q;
                    float xk = xk4[q];
                    acc[t][0].x = fmaf(xk, w0.x, acc[t][0].x);
                    acc[t][0].y = fmaf(xk, w0.y, acc[t][0].y);
                    acc[t][0].z = fmaf(xk, w0.z, acc[t][0].z);
                    acc[t][0].w = fmaf(xk, w0.w, acc[t][0].w);
                    acc[t][1].x = fmaf(xk, w1.x, acc[t][1].x);
                    acc[t][1].y = fmaf(xk, w1.y, acc[t][1].y);
                    acc[t][1].z = fmaf(xk, w1.z, acc[t][1].z);
                    acc[t][1].w = fmaf(xk, w1.w, acc[t][1].w);
                }
            }
        }
    }

    // Store
    #pragma unroll
    for (int t = 0; t < TN; t++) {
        int nl = nrow * TN + t;
        int n = base + nl;
        if (n < NN) {
            if (MODE_OUT == 1) {
                float r = sRS[nl];
                #pragma unroll
                for (int c = 0; c < 2; c++) {
                    acc[t][c].x *= r; acc[t][c].y *= r;
                    acc[t][c].z *= r; acc[t][c].w *= r;
                }
            }
            *(float4*)&out[(size_t)n * J + 8 * jv]     = acc[t][0];
            *(float4*)&out[(size_t)n * J + 8 * jv + 4] = acc[t][1];
        }
    }
}

// ---------------------------------------------------------------------------
// Layer-2 epilogue: z = agg2*rs_in + b2 (to output); t3 = z * rs_out
// ---------------------------------------------------------------------------
__global__ void epilogue_kernel(const float* __restrict__ b2, float* __restrict__ z_out) {
    int i = blockIdx.x * blockDim.x + threadIdx.x;
    if (i >= NN * 8) return;
    int n = i >> 3;
    int kc = i & 7;
    float rin  = g_scratch[OFF_RS_IN + n];
    float rout = g_scratch[OFF_RS_OUT + n];
    float4 a = *(const float4*)&g_scratch[OFF_AGG2 + (size_t)n * 32 + 4 * kc];
    float4 b = __ldg((const float4*)&b2[4 * kc]);
    float4 z;
    z.x = fmaf(a.x, rin, b.x);
    z.y = fmaf(a.y, rin, b.y);
    z.z = fmaf(a.z, rin, b.z);
    z.w = fmaf(a.w, rin, b.w);
    *(float4*)&z_out[(size_t)n * 32 + 4 * kc] = z;
    float4 t;
    t.x = z.x * rout; t.y = z.y * rout; t.z = z.z * rout; t.w = z.w * rout;
    *(float4*)&g_scratch[OFF_T3 + (size_t)n * 32 + 4 * kc] = t;
}

// ---------------------------------------------------------------------------
extern "C" void kernel_launch(void* const* d_in, const int* in_sizes, int n_in,
                              void* d_out, int out_size)
{
    const float* features = (const float*)d_in[0];
    const int*   src      = (const int*)d_in[1];
    const int*   dst      = (const int*)d_in[2];
    const float* W1       = (const float*)d_in[3];
    const float* b1       = (const float*)d_in[4];
    const float* W2       = (const float*)d_in[5];
    const float* b2       = (const float*)d_in[6];
    const float* W3       = (const float*)d_in[7];
    const float* b3       = (const float*)d_in[8];

    float* z_out = (float*)d_out;                    // [50000, 32]
    float* recon = (float*)d_out + (size_t)NN * 32;  // [50000, 128]

    float* sp = nullptr;
    cudaGetSymbolAddress((void**)&sp, g_scratch);
    float* rs_out = sp + OFF_RS_OUT;
    float* rs_in  = sp + OFF_RS_IN;
    float* t1     = sp + OFF_T1;
    float* agg1   = sp + OFF_AGG1;
    float* t2     = sp + OFF_T2;
    float* agg2   = sp + OFF_AGG2;
    float* t3     = sp + OFF_T3;
    float* agg3   = sp + OFF_AGG3;

    const int TB = 256;

    // CSR build + norms
    zero_kernel<<<(IZERO / 4 + TB - 1) / TB, TB>>>();
    count_kernel<<<(NE + TB - 1) / TB, TB>>>(src, dst);
    rsqrt_kernel<<<(NN + TB - 1) / TB, TB>>>();      // reads counts (before fill)
    scan_kernel<<<1, SCAN_T>>>();
    fill_kernel<<<(NE + TB - 1) / TB, TB>>>(src, dst);  // consumes count_dst

    // Layer 1: t1 = (X @ W1) * rs_out ; agg1 = A t1       (TN=8, NB=256)
    gemm_kernel<128, 64, 32, 8, 0, 1><<<(NN + 255) / 256, TB>>>(
        features, W1, nullptr, nullptr, rs_out, nullptr, t1);
    pull_spmm<64><<<(NN * 16 + TB - 1) / TB, TB>>>(t1, agg1);

    // Layer 2: t2 = (relu(agg1*rs_in + b1) @ W2) * rs_out ; agg2 = A t2  (TN=4, NB=256)
    gemm_kernel<64, 32, 32, 4, 1, 1><<<(NN + 255) / 256, TB>>>(
        agg1, W2, rs_in, b1, rs_out, nullptr, t2);
    pull_spmm<32><<<(NN * 8 + TB - 1) / TB, TB>>>(t2, agg2);

    // z = agg2*rs_in + b2 (output) ; t3 = z * rs_out
    epilogue_kernel<<<(NN * 8 + TB - 1) / TB, TB>>>(b2, z_out);

    // Layer 3: agg3 = A t3 ; recon = (agg3*rs_in) @ W3 + b3   (TN=8, NB=128)
    pull_spmm<32><<<(NN * 8 + TB - 1) / TB, TB>>>(t3, agg3);
    gemm_kernel<32, 128, 32, 8, 2, 2><<<(NN + 127) / 128, TB>>>(
        agg3, W3, rs_in, nullptr, nullptr, b3, recon);
}

// round 6
// speedup vs baseline: 1.2561x; 1.2561x over previous
#include <cuda_runtime.h>

// Problem constants
#define NN 50000
#define NE 600000

// Float scratch (no zeroing needed: every buffer fully overwritten each replay)
#define OFF_RS_OUT 0
#define OFF_RS_IN  50000
#define OFF_T1     100000            // 50000*64
#define OFF_AGG1   3300000           // 50000*64
#define OFF_T2     6500000           // 50000*32
#define OFF_AGG2   8100000           // 50000*32
#define OFF_T3     9700000           // 50000*32
#define OFF_AGG3   11300000          // 50000*32
#define SCRATCH_TOTAL 12900000       // 51.6 MB

// Int scratch for CSR
#define ICNT_SRC 0                   // 50000 (out-degree counts)
#define ICNT_DST 50000               // 50000 (in-degree counts; consumed by fill)
#define IOFFS    100000              // 50001 (exclusive scan of in-degrees)
#define ICSR     150004              // 600000 (src ids grouped by dst)
#define IBSUM    750004              // 256 block sums / bases
#define INT_TOTAL 750260
#define IZERO    100000              // zero [0, IZERO) ints each replay

#define NBLK 196                     // ceil(50000/256)

__device__ __align__(16) float g_scratch[SCRATCH_TOTAL];
__device__ __align__(16) int   g_int[INT_TOTAL];

// ---------------------------------------------------------------------------
// Zero the two count arrays (400 KB)
// ---------------------------------------------------------------------------
__global__ void zero_kernel() {
    int i = blockIdx.x * blockDim.x + threadIdx.x;
    if (i < IZERO / 4) ((int4*)g_int)[i] = make_int4(0, 0, 0, 0);
}

// ---------------------------------------------------------------------------
// Degree / CSR counts
// ---------------------------------------------------------------------------
__global__ void count_kernel(const int* __restrict__ src, const int* __restrict__ dst) {
    int i = blockIdx.x * blockDim.x + threadIdx.x;
    if (i >= NE) return;
    atomicAdd(&g_int[ICNT_SRC + __ldg(&src[i])], 1);
    atomicAdd(&g_int[ICNT_DST + __ldg(&dst[i])], 1);
}

__global__ void rsqrt_kernel() {
    int i = blockIdx.x * blockDim.x + threadIdx.x;
    if (i >= NN) return;
    g_scratch[OFF_RS_OUT + i] = rsqrtf(fmaxf((float)g_int[ICNT_SRC + i], 1.0f));
    g_scratch[OFF_RS_IN  + i] = rsqrtf(fmaxf((float)g_int[ICNT_DST + i], 1.0f));
}

// ---------------------------------------------------------------------------
// Parallel 3-phase exclusive scan of in-degree counts -> offsets
// ---------------------------------------------------------------------------
__global__ void __launch_bounds__(256) scan_blocksum() {
    int i = blockIdx.x * 256 + threadIdx.x;
    int v = (i < NN) ? g_int[ICNT_DST + i] : 0;
    #pragma unroll
    for (int o = 16; o; o >>= 1) v += __shfl_down_sync(0xffffffffu, v, o);
    __shared__ int ws[8];
    if ((threadIdx.x & 31) == 0) ws[threadIdx.x >> 5] = v;
    __syncthreads();
    if (threadIdx.x == 0) {
        int s = 0;
        #pragma unroll
        for (int k = 0; k < 8; k++) s += ws[k];
        g_int[IBSUM + blockIdx.x] = s;
    }
}

__global__ void __launch_bounds__(256) scan_bases() {
    int t = threadIdx.x;
    int v = (t < NBLK) ? g_int[IBSUM + t] : 0;
    int lane = t & 31, w = t >> 5;
    int x = v;
    #pragma unroll
    for (int o = 1; o < 32; o <<= 1) {
        int y = __shfl_up_sync(0xffffffffu, x, o);
        if (lane >= o) x += y;
    }
    __shared__ int ws[8], wb[8];
    if (lane == 31) ws[w] = x;
    __syncthreads();
    if (t == 0) {
        int r = 0;
        #pragma unroll
        for (int k = 0; k < 8; k++) { wb[k] = r; r += ws[k]; }
    }
    __syncthreads();
    int excl = x - v + wb[w];
    if (t < NBLK) g_int[IBSUM + t] = excl;   // overwrite: exclusive block base
}

__global__ void __launch_bounds__(256) scan_final() {
    int i = blockIdx.x * 256 + threadIdx.x;
    int v = (i < NN) ? g_int[ICNT_DST + i] : 0;
    int lane = threadIdx.x & 31, w = threadIdx.x >> 5;
    int x = v;
    #pragma unroll
    for (int o = 1; o < 32; o <<= 1) {
        int y = __shfl_up_sync(0xffffffffu, x, o);
        if (lane >= o) x += y;
    }
    __shared__ int ws[8], wb[8];
    if (lane == 31) ws[w] = x;
    __syncthreads();
    if (threadIdx.x == 0) {
        int r = 0;
        #pragma unroll
        for (int k = 0; k < 8; k++) { wb[k] = r; r += ws[k]; }
    }
    __syncthreads();
    int excl = x - v + wb[w] + g_int[IBSUM + blockIdx.x];
    if (i < NN) g_int[IOFFS + i] = excl;
    if (i == NN) g_int[IOFFS + NN] = NE;
}

// ---------------------------------------------------------------------------
// CSR fill: consumes count_dst via atomicSub (rsqrt + scan must run first)
// ---------------------------------------------------------------------------
__global__ void fill_kernel(const int* __restrict__ src, const int* __restrict__ dst) {
    int i = blockIdx.x * blockDim.x + threadIdx.x;
    if (i >= NE) return;
    int s = __ldg(&src[i]);
    int d = __ldg(&dst[i]);
    int c = atomicSub(&g_int[ICNT_DST + d], 1);
    g_int[ICSR + g_int[IOFFS + d] + c - 1] = s;
}

// ---------------------------------------------------------------------------
// Pull-mode SpMM: agg[n, :] = sum over in-edges of tin[src, :]
// One group of G = F/4 threads per dst node; register accumulate, one store.
// ---------------------------------------------------------------------------
template<int F>
__global__ void __launch_bounds__(256) pull_spmm(const float* __restrict__ tin,
                                                 float* __restrict__ agg)
{
    constexpr int G = F / 4;
    int gid = (blockIdx.x * 256 + threadIdx.x) / G;
    int lane = threadIdx.x % G;
    if (gid >= NN) return;
    int s0 = g_int[IOFFS + gid];
    int s1 = g_int[IOFFS + gid + 1];
    const int* csr = g_int + ICSR;
    float4 acc = make_float4(0.f, 0.f, 0.f, 0.f);
    int j = s0;
    for (; j + 2 <= s1; j += 2) {
        int sa = __ldg(&csr[j]);
        int sb = __ldg(&csr[j + 1]);
        float4 va = __ldg((const float4*)(tin + (size_t)sa * F + 4 * lane));
        float4 vb = __ldg((const float4*)(tin + (size_t)sb * F + 4 * lane));
        acc.x += va.x; acc.y += va.y; acc.z += va.z; acc.w += va.w;
        acc.x += vb.x; acc.y += vb.y; acc.z += vb.z; acc.w += vb.w;
    }
    if (j < s1) {
        int sa = __ldg(&csr[j]);
        float4 va = __ldg((const float4*)(tin + (size_t)sa * F + 4 * lane));
        acc.x += va.x; acc.y += va.y; acc.z += va.z; acc.w += va.w;
    }
    *(float4*)(agg + (size_t)gid * F + 4 * lane) = acc;
}

// ---------------------------------------------------------------------------
// Register-tiled GEMM, transposed X tile (conflict-free LDS.128 everywhere):
//   out[n, :J] = f_out( f_in(X[n, :K]) @ W )
//   Thread tile: TN nodes x 8 columns. sX stored as [k][node], stride NB.
//   MODE_IN : 0 raw, 1 relu(v*rs_in[n] + bin[k]), 2 v*rs_in[n]
//   MODE_OUT: 0 raw, 1 *rs_out[n],               2 +bout[j]
// ---------------------------------------------------------------------------
template<int K, int J, int KC, int TN, int MODE_IN, int MODE_OUT>
__global__ void __launch_bounds__(256) gemm_kernel(
    const float* __restrict__ X, const float* __restrict__ W,
    const float* __restrict__ rs_in, const float* __restrict__ bin,
    const float* __restrict__ rs_out, const float* __restrict__ bout,
    float* __restrict__ out)
{
    constexpr int JV = J / 8;            // column lanes (8 cols each)
    constexpr int NT = 256 / JV;         // thread rows
    constexpr int NB = NT * TN;          // nodes per block
    constexpr int XST = NB;              // transposed row stride

    __shared__ float sW[KC * J];
    __shared__ float sX[KC * XST];       // [k][node]
    __shared__ float sRS[NB];

    const int nrow = threadIdx.x / JV;
    const int jv   = threadIdx.x % JV;
    const int base = blockIdx.x * NB;

    if (MODE_OUT == 1 && threadIdx.x < NB) {
        int n = base + threadIdx.x;
        sRS[threadIdx.x] = (n < NN) ? __ldg(&rs_out[n]) : 0.f;
    }

    float4 acc[TN][2];
    #pragma unroll
    for (int t = 0; t < TN; t++)
        #pragma unroll
        for (int c = 0; c < 2; c++) {
            if (MODE_OUT == 2) acc[t][c] = __ldg((const float4*)&bout[8 * jv + 4 * c]);
            else               acc[t][c] = make_float4(0.f, 0.f, 0.f, 0.f);
        }

    #pragma unroll 1
    for (int k0 = 0; k0 < K; k0 += KC) {
        __syncthreads();
        // Stage W chunk
        for (int i = threadIdx.x; i < KC * J / 4; i += 256)
            ((float4*)sW)[i] = __ldg(&((const float4*)(W + (size_t)k0 * J))[i]);
        // Stage X chunk TRANSPOSED: sX[k][node]
        for (int i = threadIdx.x; i < NB * (KC / 4); i += 256) {
            int nl = i % NB;             // consecutive threads -> consecutive nodes
            int kc = i / NB;
            int n = base + nl;
            float4 v = make_float4(0.f, 0.f, 0.f, 0.f);
            if (n < NN) {
                v = __ldg((const float4*)&X[(size_t)n * K + k0 + 4 * kc]);
                if (MODE_IN == 1) {
                    float r = __ldg(&rs_in[n]);
                    float4 b = __ldg((const float4*)&bin[k0 + 4 * kc]);
                    v.x = fmaxf(fmaf(v.x, r, b.x), 0.f);
                    v.y = fmaxf(fmaf(v.y, r, b.y), 0.f);
                    v.z = fmaxf(fmaf(v.z, r, b.z), 0.f);
                    v.w = fmaxf(fmaf(v.w, r, b.w), 0.f);
                } else if (MODE_IN == 2) {
                    float r = __ldg(&rs_in[n]);
                    v.x *= r; v.y *= r; v.z *= r; v.w *= r;
                }
            }
            sX[(4 * kc + 0) * XST + nl] = v.x;
            sX[(4 * kc + 1) * XST + nl] = v.y;
            sX[(4 * kc + 2) * XST + nl] = v.z;
            sX[(4 * kc + 3) * XST + nl] = v.w;
        }
        __syncthreads();

        #pragma unroll 4
        for (int k = 0; k < KC; k++) {
            float4 w0 = *(const float4*)&sW[k * J + 8 * jv];
            float4 w1 = *(const float4*)&sW[k * J + 8 * jv + 4];
            #pragma unroll
            for (int tt = 0; tt < TN / 4; tt++) {
                float4 xa = *(const float4*)&sX[k * XST + nrow * TN + 4 * tt];
                float xk4[4] = {xa.x, xa.y, xa.z, xa.w};
                #pragma unroll
                for (int q = 0; q < 4; q++) {
                    int t = 4 * tt + q;
                    float xk = xk4[q];
                    acc[t][0].x = fmaf(xk, w0.x, acc[t][0].x);
                    acc[t][0].y = fmaf(xk, w0.y, acc[t][0].y);
                    acc[t][0].z = fmaf(xk, w0.z, acc[t][0].z);
                    acc[t][0].w = fmaf(xk, w0.w, acc[t][0].w);
                    acc[t][1].x = fmaf(xk, w1.x, acc[t][1].x);
                    acc[t][1].y = fmaf(xk, w1.y, acc[t][1].y);
                    acc[t][1].z = fmaf(xk, w1.z, acc[t][1].z);
                    acc[t][1].w = fmaf(xk, w1.w, acc[t][1].w);
                }
            }
        }
    }

    // Store
    #pragma unroll
    for (int t = 0; t < TN; t++) {
        int nl = nrow * TN + t;
        int n = base + nl;
        if (n < NN) {
            if (MODE_OUT == 1) {
                float r = sRS[nl];
                #pragma unroll
                for (int c = 0; c < 2; c++) {
                    acc[t][c].x *= r; acc[t][c].y *= r;
                    acc[t][c].z *= r; acc[t][c].w *= r;
                }
            }
            *(float4*)&out[(size_t)n * J + 8 * jv]     = acc[t][0];
            *(float4*)&out[(size_t)n * J + 8 * jv + 4] = acc[t][1];
        }
    }
}

// ---------------------------------------------------------------------------
// Layer-2 epilogue: z = agg2*rs_in + b2 (to output); t3 = z * rs_out
// ---------------------------------------------------------------------------
__global__ void epilogue_kernel(const float* __restrict__ b2, float* __restrict__ z_out) {
    int i = blockIdx.x * blockDim.x + threadIdx.x;
    if (i >= NN * 8) return;
    int n = i >> 3;
    int kc = i & 7;
    float rin  = g_scratch[OFF_RS_IN + n];
    float rout = g_scratch[OFF_RS_OUT + n];
    float4 a = *(const float4*)&g_scratch[OFF_AGG2 + (size_t)n * 32 + 4 * kc];
    float4 b = __ldg((const float4*)&b2[4 * kc]);
    float4 z;
    z.x = fmaf(a.x, rin, b.x);
    z.y = fmaf(a.y, rin, b.y);
    z.z = fmaf(a.z, rin, b.z);
    z.w = fmaf(a.w, rin, b.w);
    *(float4*)&z_out[(size_t)n * 32 + 4 * kc] = z;
    float4 t;
    t.x = z.x * rout; t.y = z.y * rout; t.z = z.z * rout; t.w = z.w * rout;
    *(float4*)&g_scratch[OFF_T3 + (size_t)n * 32 + 4 * kc] = t;
}

// ---------------------------------------------------------------------------
extern "C" void kernel_launch(void* const* d_in, const int* in_sizes, int n_in,
                              void* d_out, int out_size)
{
    const float* features = (const float*)d_in[0];
    const int*   src      = (const int*)d_in[1];
    const int*   dst      = (const int*)d_in[2];
    const float* W1       = (const float*)d_in[3];
    const float* b1       = (const float*)d_in[4];
    const float* W2       = (const float*)d_in[5];
    const float* b2       = (const float*)d_in[6];
    const float* W3       = (const float*)d_in[7];
    const float* b3       = (const float*)d_in[8];

    float* z_out = (float*)d_out;                    // [50000, 32]
    float* recon = (float*)d_out + (size_t)NN * 32;  // [50000, 128]

    float* sp = nullptr;
    cudaGetSymbolAddress((void**)&sp, g_scratch);
    float* rs_out = sp + OFF_RS_OUT;
    float* rs_in  = sp + OFF_RS_IN;
    float* t1     = sp + OFF_T1;
    float* agg1   = sp + OFF_AGG1;
    float* t2     = sp + OFF_T2;
    float* agg2   = sp + OFF_AGG2;
    float* t3     = sp + OFF_T3;
    float* agg3   = sp + OFF_AGG3;

    const int TB = 256;

    // CSR build + norms
    zero_kernel<<<(IZERO / 4 + TB - 1) / TB, TB>>>();
    count_kernel<<<(NE + TB - 1) / TB, TB>>>(src, dst);
    rsqrt_kernel<<<(NN + TB - 1) / TB, TB>>>();      // reads counts (before fill)
    scan_blocksum<<<NBLK, 256>>>();
    scan_bases<<<1, 256>>>();
    scan_final<<<NBLK, 256>>>();
    fill_kernel<<<(NE + TB - 1) / TB, TB>>>(src, dst);  // consumes count_dst

    // Layer 1: t1 = (X @ W1) * rs_out ; agg1 = A t1       (TN=8, NB=256)
    gemm_kernel<128, 64, 32, 8, 0, 1><<<(NN + 255) / 256, TB>>>(
        features, W1, nullptr, nullptr, rs_out, nullptr, t1);
    pull_spmm<64><<<(NN * 16 + TB - 1) / TB, TB>>>(t1, agg1);

    // Layer 2: t2 = (relu(agg1*rs_in + b1) @ W2) * rs_out ; agg2 = A t2  (TN=4, NB=256)
    gemm_kernel<64, 32, 32, 4, 1, 1><<<(NN + 255) / 256, TB>>>(
        agg1, W2, rs_in, b1, rs_out, nullptr, t2);
    pull_spmm<32><<<(NN * 8 + TB - 1) / TB, TB>>>(t2, agg2);

    // z = agg2*rs_in + b2 (output) ; t3 = z * rs_out
    epilogue_kernel<<<(NN * 8 + TB - 1) / TB, TB>>>(b2, z_out);

    // Layer 3: agg3 = A t3 ; recon = (agg3*rs_in) @ W3 + b3   (TN=8, NB=128)
    pull_spmm<32><<<(NN * 8 + TB - 1) / TB, TB>>>(t3, agg3);
    gemm_kernel<32, 128, 32, 8, 2, 2><<<(NN + 127) / 128, TB>>>(
        agg3, W3, rs_in, nullptr, nullptr, b3, recon);
}